// round 13
// baseline (speedup 1.0000x reference)
#include <cuda_runtime.h>
#include <cuda_bf16.h>
#include <cstdint>
#include <cstddef>

// ---------------- problem constants ----------------
constexpr int N_  = 16;
constexpr int D_  = 16;
constexpr int S_  = 112;
constexpr int SS_ = S_ * S_;          // 12544
constexpr int M_  = 2;
constexpr int V_  = 7829;
constexpr int K_  = 512;
constexpr int NM_ = N_ * M_;          // 32
constexpr int NCH = 16;               // v-chunks
constexpr int VCH = 490;              // chunk size (16*490 = 7840 >= V_)
constexpr int CAP = 32;               // candidate slots per (k, chunk)
constexpr int CYB = 16;               // k_cyc grid.y
constexpr int TILE = 14;              // k_fuse v-tile (35 tiles * 14 = 490)
constexpr float TSCALE = 20.0f;       // 1/T
constexpr float THRESH = -13.0f;      // keep 20*(sim - rmax) > -13 (dropped mass ~2e-6)
constexpr float SH     = 60.0f;       // fixed column-softmax shift (cancels in ratio)

// ---------------- static device scratch ----------------
__device__ __nv_bfloat16 g_bt[(size_t)NM_ * V_ * K_];   // [nm][v][k] B-tilde (bf16)
__device__ float g_sampled[N_ * K_ * D_];
__device__ float g_fx[N_ * K_], g_fy[N_ * K_];
__device__ float g_rpmax[NM_ * NCH * K_];
__device__ float g_rpsum[NM_ * NCH * K_];
__device__ float g_tk[NM_ * K_];                  // -20*rmax[k]
__device__ float g_rk[NM_ * K_];                  // 1/rsum[k]
__device__ int   g_cnt[NM_ * NCH * K_];
__device__ uint2 g_cand[(size_t)NM_ * NCH * K_ * CAP];   // {v, e=exp(20sim+tk)}
__device__ float g_partial[NM_ * CYB];
__device__ int   g_is64;

// ---------------- fast exp: pure FMA, branchless, ~1.3e-6 rel err ----------------
static __device__ __forceinline__ float fexp(float x) {
    float y = x * 1.4426950408889634f;           // x/ln2
    y = fminf(y, 126.0f);
    y = fmaxf(y, -127.0f);                        // underflow -> ~0
    float fl = floorf(y);
    float f  = y - fl;                            // [0,1)
    float p = 1.5252733804e-5f;
    p = fmaf(p, f, 1.5403530393e-4f);
    p = fmaf(p, f, 1.3333558146e-3f);
    p = fmaf(p, f, 9.6181291076e-3f);
    p = fmaf(p, f, 5.5504108664e-2f);
    p = fmaf(p, f, 2.4022650696e-1f);
    p = fmaf(p, f, 6.9314718056e-1f);
    p = fmaf(p, f, 1.0f);
    return __int_as_float(__float_as_int(p) + (((int)fl) << 23));
}

// 16-term dot of sampled row (regs) with mesh row (broadcast float4 loads)
static __device__ __forceinline__ float dot16(const float* sk, const float4* mb, int v) {
    float4 m0 = __ldg(&mb[v * 4 + 0]), m1 = __ldg(&mb[v * 4 + 1]);
    float4 m2 = __ldg(&mb[v * 4 + 2]), m3 = __ldg(&mb[v * 4 + 3]);
    float s0 =          sk[0]  * m0.x;   s0 = fmaf(sk[1],  m0.y, s0);
    float s1 =          sk[2]  * m0.z;   s1 = fmaf(sk[3],  m0.w, s1);
    float s2 =          sk[4]  * m1.x;   s2 = fmaf(sk[5],  m1.y, s2);
    float s3 =          sk[6]  * m1.z;   s3 = fmaf(sk[7],  m1.w, s3);
    s0 = fmaf(sk[8],  m2.x, s0);  s1 = fmaf(sk[9],  m2.y, s1);
    s2 = fmaf(sk[10], m2.z, s2);  s3 = fmaf(sk[11], m2.w, s3);
    s0 = fmaf(sk[12], m3.x, s0);  s1 = fmaf(sk[13], m3.y, s1);
    s2 = fmaf(sk[14], m3.z, s2);  s3 = fmaf(sk[15], m3.w, s3);
    return (s0 + s1) + (s2 + s3);
}

// ---------------- K0: detect int64 vs int32 indices ----------------
__global__ void k_detect(const int* __restrict__ w) {
    __shared__ int s_allzero;
    if (threadIdx.x == 0) s_allzero = 1;
    __syncthreads();
    int nz = 0;
    for (int i = threadIdx.x * 2 + 1; i < N_ * K_; i += blockDim.x * 2)
        if (w[i] != 0) nz = 1;
    if (nz) atomicAnd(&s_allzero, 0);
    __syncthreads();
    if (threadIdx.x == 0) g_is64 = s_allzero;
}

// ---------------- K1: gather + normalize sampled embeddings ----------------
__global__ void k_sample(const float* __restrict__ pix, const void* __restrict__ idxraw) {
    int t = blockIdx.x * blockDim.x + threadIdx.x;
    if (t >= N_ * K_) return;
    long long idx;
    if (g_is64) idx = ((const long long*)idxraw)[t];
    else        idx = (long long)((const int*)idxraw)[t];
    int n = t / K_;
    int p = (int)idx;
    g_fx[t] = (float)(p / S_);
    g_fy[t] = (float)(p % S_);
    const float* base = pix + (size_t)n * D_ * SS_ + p;
    float v[16]; float ss = 0.f;
#pragma unroll
    for (int d = 0; d < 16; d++) { v[d] = base[(size_t)d * SS_]; ss = fmaf(v[d], v[d], ss); }
    float inv = 1.0f / fmaxf(sqrtf(ss), 1e-6f);
#pragma unroll
    for (int d = 0; d < 16; d++) g_sampled[t * 16 + d] = v[d] * inv;
}

// ---------------- K2: on-the-fly sim, per-chunk row max (no stores) ----------------
__global__ void __launch_bounds__(512) k_simmax(const float* __restrict__ mesh) {
    int nm = blockIdx.x, ch = blockIdx.y;
    int k  = threadIdx.x;
    int n = nm / M_, m = nm % M_;
    float sk[16];
    const float* sp = &g_sampled[(n * K_ + k) * 16];
#pragma unroll
    for (int d = 0; d < 16; d++) sk[d] = sp[d];
    int v0 = ch * VCH;
    int v1 = min(v0 + VCH, V_);
    const float4* mb = (const float4*)(mesh + (size_t)m * V_ * D_);
    float mx0 = -1e30f, mx1 = -1e30f, mx2 = -1e30f, mx3 = -1e30f;
    int v = v0;
    for (; v + 3 < v1; v += 4) {
        mx0 = fmaxf(mx0, dot16(sk, mb, v));
        mx1 = fmaxf(mx1, dot16(sk, mb, v + 1));
        mx2 = fmaxf(mx2, dot16(sk, mb, v + 2));
        mx3 = fmaxf(mx3, dot16(sk, mb, v + 3));
    }
    for (; v < v1; v++) mx0 = fmaxf(mx0, dot16(sk, mb, v));
    g_rpmax[(nm * NCH + ch) * K_ + k] = fmaxf(fmaxf(mx0, mx1), fmaxf(mx2, mx3));
}

// ---------------- K2b: combine chunk maxes -> tk ----------------
__global__ void k_rowmax() {
    int t = blockIdx.x * blockDim.x + threadIdx.x;
    if (t >= NM_ * K_) return;
    int nm = t / K_, k = t % K_;
    float mx = -1e30f;
#pragma unroll
    for (int c = 0; c < NCH; c++) mx = fmaxf(mx, g_rpmax[(nm * NCH + c) * K_ + k]);
    g_tk[t] = -TSCALE * mx;
}

// ---------------- K3: fused recompute + column softmax + B-tilde + candidates ----------------
// Block (nm, ch): 512 threads = full k-row. Tiled over TILE=14 v's:
//   phase1: 14 independent dot/exp/warp-reduce chains (pipelined, no barrier)
//   sync; phase2: cross-warp sums for all 14 v at once (segmented shfl)
//   sync; phase3: write B = e/csum (bf16)
__global__ void __launch_bounds__(512) k_fuse(const float* __restrict__ mesh) {
    __shared__ float swarp[16][TILE];
    __shared__ float scsum[TILE];
    int nm = blockIdx.x, ch = blockIdx.y;
    int k  = threadIdx.x;
    int n = nm / M_, m = nm % M_;
    int wid = k >> 5, lane = k & 31;
    float sk[16];
    const float* sp = &g_sampled[(n * K_ + k) * 16];
#pragma unroll
    for (int d = 0; d < 16; d++) sk[d] = sp[d];
    float tk = g_tk[nm * K_ + k];
    int v0 = ch * VCH;
    int v1 = min(v0 + VCH, V_);
    const float4* mb = (const float4*)(mesh + (size_t)m * V_ * D_);
    uint2* cl = g_cand + ((size_t)((nm * NCH + ch) * K_ + k)) * CAP;
    __nv_bfloat16* bbase = g_bt + (size_t)nm * V_ * K_ + k;
    int cnt = 0; float rs = 0.f;

    for (int vt = v0; vt < v0 + VCH; vt += TILE) {
        float e[TILE];
        // phase 1: dots, exps, warp sums, candidates (independent chains)
#pragma unroll
        for (int i = 0; i < TILE; i++) {
            int v = vt + i;
            float s = (v < v1) ? dot16(sk, mb, v) : -1e30f;
            e[i] = fexp(fmaf(TSCALE, s, -SH));
            float ws = e[i];
#pragma unroll
            for (int o = 16; o > 0; o >>= 1) ws += __shfl_xor_sync(0xffffffffu, ws, o);
            if (lane == 0) swarp[wid][i] = ws;
            float t = fmaf(TSCALE, s, tk);
            if (t > THRESH) {
                float er = fexp(t);
                rs += er;
                if (cnt < CAP) cl[cnt] = make_uint2((unsigned)v, __float_as_uint(er));
                cnt++;
            }
        }
        __syncthreads();
        // phase 2: cross-warp reduce, 16 threads per v (segmented shfl width 16)
        if (k < 16 * TILE) {
            int i = k >> 4, w = k & 15;
            float val = swarp[w][i];
#pragma unroll
            for (int o = 8; o > 0; o >>= 1) val += __shfl_xor_sync(0xffffffffu, val, o, 16);
            if (w == 0) scsum[i] = val;
        }
        __syncthreads();
        // phase 3: write B-tilde
#pragma unroll
        for (int i = 0; i < TILE; i++) {
            int v = vt + i;
            if (v < v1)
                bbase[(size_t)v * K_] = __float2bfloat16(__fdividef(e[i], scsum[i]));
        }
        __syncthreads();
    }
    g_cnt[(nm * NCH + ch) * K_ + k] = min(cnt, CAP);
    g_rpsum[(nm * NCH + ch) * K_ + k] = rs;
}

// ---------------- K3b: finalize rows -> rk ----------------
__global__ void k_rowfin() {
    int t = blockIdx.x * blockDim.x + threadIdx.x;
    if (t >= NM_ * K_) return;
    int nm = t / K_, k = t % K_;
    float s = 0.f;
#pragma unroll
    for (int c = 0; c < NCH; c++) s += g_rpsum[(nm * NCH + c) * K_ + k];
    g_rk[t] = 1.0f / s;
}

// ---------------- K5: sparse cycle (pure FMA) + fused loss ----------------
__global__ void __launch_bounds__(256) k_cyc() {
    __shared__ float sfx[K_], sfy[K_];
    __shared__ float red[256];
    int nm = blockIdx.x, by = blockIdx.y;
    int n = nm / M_;
    int tid = threadIdx.x, w = tid >> 5, lane = tid & 31;
    for (int i = tid; i < K_; i += 256) {
        sfx[i] = g_fx[n * K_ + i];
        sfy[i] = g_fy[n * K_ + i];
    }
    __syncthreads();

    float part = 0.f;
#pragma unroll 1
    for (int i = 0; i < 4; i++) {
        int k = by * 32 + w * 4 + i;
        float rkk = g_rk[nm * K_ + k];
        float acc[16];
#pragma unroll
        for (int j = 0; j < 16; j++) acc[j] = 0.f;

        for (int ch = 0; ch < NCH; ch++) {
            int base = (nm * NCH + ch) * K_ + k;
            int cnt = g_cnt[base];
            const uint2* cl = g_cand + (size_t)base * CAP;
            if (cnt == 0) continue;
            uint2 ce = cl[0];
            for (int c = 0; c < cnt; c++) {
                uint2 ce_next = (c + 1 < cnt) ? cl[c + 1] : ce;   // prefetch
                float wv = __uint_as_float(ce.y) * rkk;           // A[k,v]
                const uint32_t* row =
                    (const uint32_t*)(g_bt + ((size_t)nm * V_ + ce.x) * K_);
                uint32_t rw[8];
#pragma unroll
                for (int j = 0; j < 8; j++) rw[j] = __ldg(&row[j * 32 + lane]);
#pragma unroll
                for (int j = 0; j < 8; j++) {
                    float2 f = __bfloat1622float2(*reinterpret_cast<__nv_bfloat162*>(&rw[j]));
                    acc[2 * j]     = fmaf(wv, f.x, acc[2 * j]);
                    acc[2 * j + 1] = fmaf(wv, f.y, acc[2 * j + 1]);
                }
                ce = ce_next;
            }
        }

        float xk = sfx[k], yk = sfy[k];
#pragma unroll
        for (int j = 0; j < 8; j++) {
            int q0 = 2 * (j * 32 + lane);
            float dx0 = xk - sfx[q0], dy0 = yk - sfy[q0];
            float dist0 = fmaf(dx0, dx0, dy0 * dy0);
            float wt0 = dist0 * acc[2 * j];
            part = fmaf(wt0, wt0, part);
            float dx1 = xk - sfx[q0 + 1], dy1 = yk - sfy[q0 + 1];
            float dist1 = fmaf(dx1, dx1, dy1 * dy1);
            float wt1 = dist1 * acc[2 * j + 1];
            part = fmaf(wt1, wt1, part);
        }
    }
    red[tid] = part;
    __syncthreads();
    for (int o = 128; o > 0; o >>= 1) {
        if (tid < o) red[tid] += red[tid + o];
        __syncthreads();
    }
    if (tid == 0) g_partial[nm * CYB + by] = red[0];
}

// ---------------- K6: final sqrt + mean ----------------
__global__ void k_final(float* __restrict__ out) {
    int t = threadIdx.x;           // 32 threads, one per nm
    float s = 0.f;
#pragma unroll
    for (int pr = 0; pr < CYB; pr++) s += g_partial[t * CYB + pr];
    float l = sqrtf(s);
#pragma unroll
    for (int o = 16; o > 0; o >>= 1) l += __shfl_xor_sync(0xffffffffu, l, o);
    if (t == 0) out[0] = l / (float)NM_;
}

// ---------------- launch ----------------
extern "C" void kernel_launch(void* const* d_in, const int* in_sizes, int n_in,
                              void* d_out, int out_size) {
    const float* pix  = (const float*)d_in[0];
    const float* mesh = (const float*)d_in[1];
    const void*  idx  = d_in[2];
    float* out = (float*)d_out;
    (void)in_sizes; (void)n_in; (void)out_size;

    k_detect<<<1, 256>>>((const int*)idx);
    k_sample<<<(N_ * K_ + 255) / 256, 256>>>(pix, idx);
    k_simmax<<<dim3(NM_, NCH), 512>>>(mesh);
    k_rowmax<<<(NM_ * K_ + 255) / 256, 256>>>();
    k_fuse<<<dim3(NM_, NCH), 512>>>(mesh);
    k_rowfin<<<(NM_ * K_ + 255) / 256, 256>>>();
    k_cyc<<<dim3(NM_, CYB), 256>>>();
    k_final<<<1, 32>>>(out);
}

// round 14
// speedup vs baseline: 1.5277x; 1.5277x over previous
#include <cuda_runtime.h>
#include <cuda_bf16.h>
#include <cstdint>
#include <cstddef>

// ---------------- problem constants ----------------
constexpr int N_  = 16;
constexpr int D_  = 16;
constexpr int S_  = 112;
constexpr int SS_ = S_ * S_;          // 12544
constexpr int M_  = 2;
constexpr int V_  = 7829;
constexpr int K_  = 512;
constexpr int NM_ = N_ * M_;          // 32
constexpr int NCH = 8;                // v-chunks
constexpr int VCH = (V_ + NCH - 1) / NCH;   // 979
constexpr int CAP = 40;               // candidate slots per (k, chunk)
constexpr int VT  = 128;              // smem v-tile
constexpr int CYB = 16;               // k_cyc grid.y
constexpr float TSCALE = 20.0f;       // 1/T
constexpr float MARG   = 0.65f;       // keep sim > rmax - MARG  (20*MARG = 13)
constexpr float SH     = 60.0f;       // fixed column-softmax shift (cancels in ratio)

// ---------------- static device scratch ----------------
__device__ __nv_bfloat16 g_bt[(size_t)NM_ * V_ * K_];   // [nm][v][k] B-tilde (bf16)
__device__ float g_csum[(size_t)NM_ * V_];              // column sums (with SH shift)
__device__ float g_sampled[N_ * K_ * D_];
__device__ float g_fx[N_ * K_], g_fy[N_ * K_];
__device__ float g_rpmax[NM_ * NCH * K_];
__device__ float g_rpsum[NM_ * NCH * K_];
__device__ float g_rk[NM_ * K_];                  // 1/rsum[k]
__device__ int   g_cnt[NM_ * NCH * K_];
__device__ uint2 g_cand[(size_t)NM_ * NCH * K_ * CAP];   // {v, s} then {v, e}
__device__ float g_partial[NM_ * CYB];
__device__ int   g_is64;

// ---------------- fast exp: pure FMA, branchless, ~1.3e-6 rel err ----------------
static __device__ __forceinline__ float fexp(float x) {
    float y = x * 1.4426950408889634f;           // x/ln2
    y = fminf(y, 126.0f);
    y = fmaxf(y, -127.0f);                        // underflow -> ~0
    float fl = floorf(y);
    float f  = y - fl;                            // [0,1)
    float p = 1.5252733804e-5f;
    p = fmaf(p, f, 1.5403530393e-4f);
    p = fmaf(p, f, 1.3333558146e-3f);
    p = fmaf(p, f, 9.6181291076e-3f);
    p = fmaf(p, f, 5.5504108664e-2f);
    p = fmaf(p, f, 2.4022650696e-1f);
    p = fmaf(p, f, 6.9314718056e-1f);
    p = fmaf(p, f, 1.0f);
    return __int_as_float(__float_as_int(p) + (((int)fl) << 23));
}

// 16-term dot: sampled row (regs) x mesh row (4 float4 broadcast from smem)
static __device__ __forceinline__ float dot16s(const float* sk, const float4* mv) {
    float4 m0 = mv[0], m1 = mv[1], m2 = mv[2], m3 = mv[3];
    float s0 =          sk[0]  * m0.x;   s0 = fmaf(sk[1],  m0.y, s0);
    float s1 =          sk[2]  * m0.z;   s1 = fmaf(sk[3],  m0.w, s1);
    float s2 =          sk[4]  * m1.x;   s2 = fmaf(sk[5],  m1.y, s2);
    float s3 =          sk[6]  * m1.z;   s3 = fmaf(sk[7],  m1.w, s3);
    s0 = fmaf(sk[8],  m2.x, s0);  s1 = fmaf(sk[9],  m2.y, s1);
    s2 = fmaf(sk[10], m2.z, s2);  s3 = fmaf(sk[11], m2.w, s3);
    s0 = fmaf(sk[12], m3.x, s0);  s1 = fmaf(sk[13], m3.y, s1);
    s2 = fmaf(sk[14], m3.z, s2);  s3 = fmaf(sk[15], m3.w, s3);
    return (s0 + s1) + (s2 + s3);
}

// ---------------- K0: detect int64 vs int32 indices ----------------
__global__ void k_detect(const int* __restrict__ w) {
    __shared__ int s_allzero;
    if (threadIdx.x == 0) s_allzero = 1;
    __syncthreads();
    int nz = 0;
    for (int i = threadIdx.x * 2 + 1; i < N_ * K_; i += blockDim.x * 2)
        if (w[i] != 0) nz = 1;
    if (nz) atomicAnd(&s_allzero, 0);
    __syncthreads();
    if (threadIdx.x == 0) g_is64 = s_allzero;
}

// ---------------- K1: gather + normalize sampled embeddings ----------------
__global__ void k_sample(const float* __restrict__ pix, const void* __restrict__ idxraw) {
    int t = blockIdx.x * blockDim.x + threadIdx.x;
    if (t >= N_ * K_) return;
    long long idx;
    if (g_is64) idx = ((const long long*)idxraw)[t];
    else        idx = (long long)((const int*)idxraw)[t];
    int n = t / K_;
    int p = (int)idx;
    g_fx[t] = (float)(p / S_);
    g_fy[t] = (float)(p % S_);
    const float* base = pix + (size_t)n * D_ * SS_ + p;
    float v[16]; float ss = 0.f;
#pragma unroll
    for (int d = 0; d < 16; d++) { v[d] = base[(size_t)d * SS_]; ss = fmaf(v[d], v[d], ss); }
    float inv = 1.0f / fmaxf(sqrtf(ss), 1e-6f);
#pragma unroll
    for (int d = 0; d < 16; d++) g_sampled[t * 16 + d] = v[d] * inv;
}

// ---------------- K1b: filler (shifts k_pass1 into the ncu capture slot) ----------------
__global__ void k_prep() {
    int t = blockIdx.x * blockDim.x + threadIdx.x;
    if (t < NM_ * CYB) g_partial[t] = 0.f;
}

// ---------------- K2: single dense pass ----------------
// Block (nm, ch), 512 threads (= full k-row). Mesh staged in smem tiles of VT v.
// Per thread: online row-softmax (running max m, rescaled sum sigma), candidate
// prelist (prune-on-full). Per v: warp partial column-sums -> smem, reduced once
// per tile into g_csum. No per-v barriers.
__global__ void __launch_bounds__(512) k_pass1(const float* __restrict__ mesh) {
    __shared__ float4 smesh[VT * 4];      // 8 KB
    __shared__ float  spart[VT][17];      // padded: conflict-free
    int nm = blockIdx.x, ch = blockIdx.y;
    int k  = threadIdx.x;
    int n = nm / M_, m_ = nm % M_;
    int wid = k >> 5, lane = k & 31;
    float sk[16];
    const float* sp = &g_sampled[(n * K_ + k) * 16];
#pragma unroll
    for (int d = 0; d < 16; d++) sk[d] = sp[d];
    int v0 = ch * VCH;
    int v1 = min(v0 + VCH, V_);
    const float4* mb = (const float4*)(mesh + (size_t)m_ * V_ * D_);
    float* csum_out = g_csum + (size_t)nm * V_;

    float m = -1e30f, sigma = 0.f;
    uint2 pre[CAP];
    int cnt = 0;

    for (int tb = v0; tb < v1; tb += VT) {
        int nv = min(VT, v1 - tb);
        // cooperative load of mesh tile + zero partials
        for (int i = k; i < nv * 4; i += 512) smesh[i] = mb[(size_t)tb * 4 + i];
        for (int i = k; i < nv * 16; i += 512) spart[i >> 4][i & 15] = 0.f;
        __syncthreads();
        for (int iv = 0; iv < nv; iv++) {
            float s = dot16s(sk, &smesh[iv * 4]);
            float e = fexp(fmaf(TSCALE, s, -SH));
            float ws = e;
#pragma unroll
            for (int o = 16; o > 0; o >>= 1) ws += __shfl_xor_sync(0xffffffffu, ws, o);
            if (lane == 0) spart[iv][wid] = ws;
            if (s > m - MARG) {
                if (s > m) { sigma = fmaf(sigma, fexp(TSCALE * (m - s)), 1.0f); m = s; }
                else sigma += fexp(TSCALE * (s - m));
                if (cnt >= CAP) {           // prune stale entries
                    float thr = m - MARG;
                    int j = 0;
                    for (int i2 = 0; i2 < cnt; i2++)
                        if (__uint_as_float(pre[i2].y) > thr) pre[j++] = pre[i2];
                    cnt = j;
                }
                if (cnt < CAP) { pre[cnt] = make_uint2((unsigned)(tb + iv), __float_as_uint(s)); cnt++; }
            }
        }
        __syncthreads();
        // column-sum reduce for this tile
        if (k < nv) {
            float cs = 0.f;
#pragma unroll
            for (int w = 0; w < 16; w++) cs += spart[k][w];
            csum_out[tb + k] = cs;
        }
        __syncthreads();
    }

    // write chunk stats + filtered prelist (as {v, s})
    int base = (nm * NCH + ch) * K_ + k;
    g_rpmax[base] = m;
    g_rpsum[base] = sigma;
    uint2* cl = g_cand + (size_t)base * CAP;
    float thr = m - MARG;
    int out = 0;
    for (int i = 0; i < cnt; i++)
        if (__uint_as_float(pre[i].y) > thr) cl[out++] = pre[i];
    g_cnt[base] = out;
}

// ---------------- K3: combine chunks -> rk; finalize candidate lists ----------------
__global__ void k_comb() {
    int t = blockIdx.x * blockDim.x + threadIdx.x;
    if (t >= NM_ * K_) return;
    int nm = t / K_, k = t % K_;
    float mstar = -1e30f;
#pragma unroll
    for (int c = 0; c < NCH; c++)
        mstar = fmaxf(mstar, g_rpmax[(nm * NCH + c) * K_ + k]);
    float sig = 0.f;
#pragma unroll
    for (int c = 0; c < NCH; c++) {
        int b = (nm * NCH + c) * K_ + k;
        sig += g_rpsum[b] * fexp(TSCALE * (g_rpmax[b] - mstar));
    }
    g_rk[t] = 1.0f / sig;
    float thr = mstar - MARG;
#pragma unroll
    for (int c = 0; c < NCH; c++) {
        int b = (nm * NCH + c) * K_ + k;
        int cn = g_cnt[b];
        uint2* cl = g_cand + (size_t)b * CAP;
        int out = 0;
        for (int i = 0; i < cn; i++) {
            uint2 e = cl[i];
            float s = __uint_as_float(e.y);
            if (s > thr)
                cl[out++] = make_uint2(e.x, __float_as_uint(fexp(TSCALE * (s - mstar))));
        }
        g_cnt[b] = out;
    }
}

// ---------------- K4: B-tilde rows (bf16), smem-staged mesh + csum ----------------
__global__ void __launch_bounds__(512) k_bt(const float* __restrict__ mesh) {
    __shared__ float4 smesh[VT * 4];      // 8 KB
    __shared__ float  srcp[VT];
    int nm = blockIdx.x, ch = blockIdx.y;
    int k  = threadIdx.x;
    int n = nm / M_, m_ = nm % M_;
    float sk[16];
    const float* sp = &g_sampled[(n * K_ + k) * 16];
#pragma unroll
    for (int d = 0; d < 16; d++) sk[d] = sp[d];
    int v0 = ch * VCH;
    int v1 = min(v0 + VCH, V_);
    const float4* mb = (const float4*)(mesh + (size_t)m_ * V_ * D_);
    const float* csum_in = g_csum + (size_t)nm * V_;
    __nv_bfloat16* bbase = g_bt + (size_t)nm * V_ * K_ + k;

    for (int tb = v0; tb < v1; tb += VT) {
        int nv = min(VT, v1 - tb);
        for (int i = k; i < nv * 4; i += 512) smesh[i] = mb[(size_t)tb * 4 + i];
        if (k < nv) srcp[k] = 1.0f / csum_in[tb + k];
        __syncthreads();
        for (int iv = 0; iv < nv; iv++) {
            float s = dot16s(sk, &smesh[iv * 4]);
            float e = fexp(fmaf(TSCALE, s, -SH));
            bbase[(size_t)(tb + iv) * K_] = __float2bfloat16(e * srcp[iv]);
        }
        __syncthreads();
    }
}

// ---------------- K5: sparse cycle (pure FMA) + fused loss ----------------
__global__ void __launch_bounds__(256) k_cyc() {
    __shared__ float sfx[K_], sfy[K_];
    __shared__ float red[256];
    int nm = blockIdx.x, by = blockIdx.y;
    int n = nm / M_;
    int tid = threadIdx.x, w = tid >> 5, lane = tid & 31;
    for (int i = tid; i < K_; i += 256) {
        sfx[i] = g_fx[n * K_ + i];
        sfy[i] = g_fy[n * K_ + i];
    }
    __syncthreads();

    float part = 0.f;
#pragma unroll 1
    for (int i = 0; i < 4; i++) {
        int k = by * 32 + w * 4 + i;
        float rkk = g_rk[nm * K_ + k];
        float acc[16];
#pragma unroll
        for (int j = 0; j < 16; j++) acc[j] = 0.f;

        for (int ch = 0; ch < NCH; ch++) {
            int base = (nm * NCH + ch) * K_ + k;
            int cnt = g_cnt[base];
            const uint2* cl = g_cand + (size_t)base * CAP;
            if (cnt == 0) continue;
            uint2 ce = cl[0];
            for (int c = 0; c < cnt; c++) {
                uint2 ce_next = (c + 1 < cnt) ? cl[c + 1] : ce;   // prefetch
                float wv = __uint_as_float(ce.y) * rkk;           // A[k,v]
                const uint32_t* row =
                    (const uint32_t*)(g_bt + ((size_t)nm * V_ + ce.x) * K_);
                uint32_t rw[8];
#pragma unroll
                for (int j = 0; j < 8; j++) rw[j] = __ldg(&row[j * 32 + lane]);
#pragma unroll
                for (int j = 0; j < 8; j++) {
                    float2 f = __bfloat1622float2(*reinterpret_cast<__nv_bfloat162*>(&rw[j]));
                    acc[2 * j]     = fmaf(wv, f.x, acc[2 * j]);
                    acc[2 * j + 1] = fmaf(wv, f.y, acc[2 * j + 1]);
                }
                ce = ce_next;
            }
        }

        float xk = sfx[k], yk = sfy[k];
#pragma unroll
        for (int j = 0; j < 8; j++) {
            int q0 = 2 * (j * 32 + lane);
            float dx0 = xk - sfx[q0], dy0 = yk - sfy[q0];
            float dist0 = fmaf(dx0, dx0, dy0 * dy0);
            float wt0 = dist0 * acc[2 * j];
            part = fmaf(wt0, wt0, part);
            float dx1 = xk - sfx[q0 + 1], dy1 = yk - sfy[q0 + 1];
            float dist1 = fmaf(dx1, dx1, dy1 * dy1);
            float wt1 = dist1 * acc[2 * j + 1];
            part = fmaf(wt1, wt1, part);
        }
    }
    red[tid] = part;
    __syncthreads();
    for (int o = 128; o > 0; o >>= 1) {
        if (tid < o) red[tid] += red[tid + o];
        __syncthreads();
    }
    if (tid == 0) g_partial[nm * CYB + by] = red[0];
}

// ---------------- K6: final sqrt + mean ----------------
__global__ void k_final(float* __restrict__ out) {
    int t = threadIdx.x;           // 32 threads, one per nm
    float s = 0.f;
#pragma unroll
    for (int pr = 0; pr < CYB; pr++) s += g_partial[t * CYB + pr];
    float l = sqrtf(s);
#pragma unroll
    for (int o = 16; o > 0; o >>= 1) l += __shfl_xor_sync(0xffffffffu, l, o);
    if (t == 0) out[0] = l / (float)NM_;
}

// ---------------- launch ----------------
extern "C" void kernel_launch(void* const* d_in, const int* in_sizes, int n_in,
                              void* d_out, int out_size) {
    const float* pix  = (const float*)d_in[0];
    const float* mesh = (const float*)d_in[1];
    const void*  idx  = d_in[2];
    float* out = (float*)d_out;
    (void)in_sizes; (void)n_in; (void)out_size;

    k_detect<<<1, 256>>>((const int*)idx);
    k_sample<<<(N_ * K_ + 255) / 256, 256>>>(pix, idx);
    k_prep<<<2, 256>>>();
    k_pass1<<<dim3(NM_, NCH), 512>>>(mesh);    // 4th launch -> ncu capture slot
    k_comb<<<(NM_ * K_ + 255) / 256, 256>>>();
    k_bt<<<dim3(NM_, NCH), 512>>>(mesh);
    k_cyc<<<dim3(NM_, CYB), 256>>>();
    k_final<<<1, 32>>>(out);
}

// round 15
// speedup vs baseline: 2.1905x; 1.4339x over previous
#include <cuda_runtime.h>
#include <cuda_bf16.h>
#include <cstdint>
#include <cstddef>

// ---------------- problem constants ----------------
constexpr int N_  = 16;
constexpr int D_  = 16;
constexpr int S_  = 112;
constexpr int SS_ = S_ * S_;          // 12544
constexpr int M_  = 2;
constexpr int V_  = 7829;
constexpr int K_  = 512;
constexpr int NM_ = N_ * M_;          // 32
constexpr int NCH = 8;                // v-chunks
constexpr int VCH = (V_ + NCH - 1) / NCH;   // 979
constexpr int CAP = 40;               // candidate slots per (k, chunk)
constexpr int VT  = 128;              // smem v-tile
constexpr int CYB = 16;               // k_cyc grid.y
constexpr float TSCALE = 20.0f;       // 1/T
constexpr float MARG   = 0.65f;       // keep sim > rmax - MARG  (20*MARG = 13)
constexpr float SH     = 60.0f;       // fixed column shift (cancels in normalize)

// ---------------- static device scratch ----------------
__device__ __nv_bfloat16 g_bt[(size_t)NM_ * V_ * K_];   // [nm][v][k]: e-tilde, then B-tilde
__device__ float g_sampled[N_ * K_ * D_];
__device__ float g_fx[N_ * K_], g_fy[N_ * K_];
__device__ float g_rpmax[NM_ * NCH * K_];
__device__ float g_rpsum[NM_ * NCH * K_];
__device__ float g_rk[NM_ * K_];                  // 1/rsum[k]
__device__ int   g_cnt[NM_ * NCH * K_];
__device__ uint2 g_cand[(size_t)NM_ * NCH * K_ * CAP];   // {v, s} then {v, e}
__device__ float g_partial[NM_ * CYB];
__device__ int   g_is64;

// 16-term dot: sampled row (regs) x mesh row (4 float4 broadcast from smem)
static __device__ __forceinline__ float dot16s(const float* sk, const float4* mv) {
    float4 m0 = mv[0], m1 = mv[1], m2 = mv[2], m3 = mv[3];
    float s0 =          sk[0]  * m0.x;   s0 = fmaf(sk[1],  m0.y, s0);
    float s1 =          sk[2]  * m0.z;   s1 = fmaf(sk[3],  m0.w, s1);
    float s2 =          sk[4]  * m1.x;   s2 = fmaf(sk[5],  m1.y, s2);
    float s3 =          sk[6]  * m1.z;   s3 = fmaf(sk[7],  m1.w, s3);
    s0 = fmaf(sk[8],  m2.x, s0);  s1 = fmaf(sk[9],  m2.y, s1);
    s2 = fmaf(sk[10], m2.z, s2);  s3 = fmaf(sk[11], m2.w, s3);
    s0 = fmaf(sk[12], m3.x, s0);  s1 = fmaf(sk[13], m3.y, s1);
    s2 = fmaf(sk[14], m3.z, s2);  s3 = fmaf(sk[15], m3.w, s3);
    return (s0 + s1) + (s2 + s3);
}

// ---------------- K0: detect int64 vs int32 indices ----------------
__global__ void k_detect(const int* __restrict__ w) {
    __shared__ int s_allzero;
    if (threadIdx.x == 0) s_allzero = 1;
    __syncthreads();
    int nz = 0;
    for (int i = threadIdx.x * 2 + 1; i < N_ * K_; i += blockDim.x * 2)
        if (w[i] != 0) nz = 1;
    if (nz) atomicAnd(&s_allzero, 0);
    __syncthreads();
    if (threadIdx.x == 0) g_is64 = s_allzero;
}

// ---------------- K1: gather + normalize sampled embeddings ----------------
__global__ void k_sample(const float* __restrict__ pix, const void* __restrict__ idxraw) {
    int t = blockIdx.x * blockDim.x + threadIdx.x;
    if (t >= N_ * K_) return;
    long long idx;
    if (g_is64) idx = ((const long long*)idxraw)[t];
    else        idx = (long long)((const int*)idxraw)[t];
    int n = t / K_;
    int p = (int)idx;
    g_fx[t] = (float)(p / S_);
    g_fy[t] = (float)(p % S_);
    const float* base = pix + (size_t)n * D_ * SS_ + p;
    float v[16]; float ss = 0.f;
#pragma unroll
    for (int d = 0; d < 16; d++) { v[d] = base[(size_t)d * SS_]; ss = fmaf(v[d], v[d], ss); }
    float inv = 1.0f / fmaxf(sqrtf(ss), 1e-6f);
#pragma unroll
    for (int d = 0; d < 16; d++) g_sampled[t * 16 + d] = v[d] * inv;
}

// ---------------- K1b: filler (keeps k_pass1 in the ncu capture slot) ----------------
__global__ void k_prep() {
    int t = blockIdx.x * blockDim.x + threadIdx.x;
    if (t < NM_ * CYB) g_partial[t] = 0.f;
}

// ---------------- K2: single dense pass ----------------
// Block (nm, ch), 512 threads (= full k-row). Mesh staged in smem tiles of VT v.
// Per (k,v): dot16 (smem) + MUFU exp + bf16 store of UNNORMALIZED e-tilde,
// plus online row-softmax stats and direct-to-global candidate list.
__global__ void __launch_bounds__(512) k_pass1(const float* __restrict__ mesh) {
    __shared__ float4 smesh[VT * 4];      // 8 KB
    int nm = blockIdx.x, ch = blockIdx.y;
    int k  = threadIdx.x;
    int n = nm / M_, m_ = nm % M_;
    float sk[16];
    const float* sp = &g_sampled[(n * K_ + k) * 16];
#pragma unroll
    for (int d = 0; d < 16; d++) sk[d] = sp[d];
    int v0 = ch * VCH;
    int v1 = min(v0 + VCH, V_);
    const float4* mb = (const float4*)(mesh + (size_t)m_ * V_ * D_);
    __nv_bfloat16* bbase = g_bt + (size_t)nm * V_ * K_ + k;
    int cbase = (nm * NCH + ch) * K_ + k;
    uint2* cl = g_cand + (size_t)cbase * CAP;

    float m = -1e30f, sigma = 0.f;
    int cnt = 0;

    for (int tb = v0; tb < v1; tb += VT) {
        int nv = min(VT, v1 - tb);
        for (int i = k; i < nv * 4; i += 512) smesh[i] = mb[(size_t)tb * 4 + i];
        __syncthreads();
        for (int iv = 0; iv < nv; iv++) {
            float s = dot16s(sk, &smesh[iv * 4]);
            bbase[(size_t)(tb + iv) * K_] =
                __float2bfloat16(__expf(fmaf(TSCALE, s, -SH)));
            if (s > m - MARG) {
                if (s > m) { sigma = fmaf(sigma, __expf(TSCALE * (m - s)), 1.0f); m = s; }
                else sigma += __expf(TSCALE * (s - m));
                if (cnt >= CAP) {               // rare: compact in place
                    float thr = m - MARG;
                    int j = 0;
                    for (int i2 = 0; i2 < cnt; i2++) {
                        uint2 e = cl[i2];
                        if (__uint_as_float(e.y) > thr) cl[j++] = e;
                    }
                    cnt = j;
                }
                if (cnt < CAP) { cl[cnt] = make_uint2((unsigned)(tb + iv), __float_as_uint(s)); cnt++; }
            }
        }
        __syncthreads();
    }
    g_rpmax[cbase] = m;
    g_rpsum[cbase] = sigma;
    g_cnt[cbase] = cnt;
}

// ---------------- K3: combine chunks -> rk; finalize candidate lists ----------------
__global__ void k_comb() {
    int t = blockIdx.x * blockDim.x + threadIdx.x;
    if (t >= NM_ * K_) return;
    int nm = t / K_, k = t % K_;
    float mstar = -1e30f;
#pragma unroll
    for (int c = 0; c < NCH; c++)
        mstar = fmaxf(mstar, g_rpmax[(nm * NCH + c) * K_ + k]);
    float sig = 0.f;
#pragma unroll
    for (int c = 0; c < NCH; c++) {
        int b = (nm * NCH + c) * K_ + k;
        sig += g_rpsum[b] * __expf(TSCALE * (g_rpmax[b] - mstar));
    }
    g_rk[t] = 1.0f / sig;
    float thr = mstar - MARG;
#pragma unroll
    for (int c = 0; c < NCH; c++) {
        int b = (nm * NCH + c) * K_ + k;
        int cn = g_cnt[b];
        uint2* cl = g_cand + (size_t)b * CAP;
        int out = 0;
        for (int i = 0; i < cn; i++) {
            uint2 e = cl[i];
            float s = __uint_as_float(e.y);
            if (s > thr)
                cl[out++] = make_uint2(e.x, __float_as_uint(__expf(TSCALE * (s - mstar))));
        }
        g_cnt[b] = out;
    }
}

// ---------------- K4: normalize e-tilde rows in place -> B-tilde ----------------
// Warp per (nm, v) row: sum 512 bf16 in fp32, scale by 1/sum, write back.
__global__ void __launch_bounds__(256) k_norm() {
    int nm = blockIdx.x;
    int v  = blockIdx.y * 8 + (threadIdx.x >> 5);
    int lane = threadIdx.x & 31;
    if (v >= V_) return;
    uint32_t* row = (uint32_t*)(g_bt + ((size_t)nm * V_ + v) * K_);
    uint4 a = ((uint4*)row)[lane];
    uint4 b = ((uint4*)row)[lane + 32];
    float s = 0.f;
    uint32_t w[8] = {a.x, a.y, a.z, a.w, b.x, b.y, b.z, b.w};
    float2 f[8];
#pragma unroll
    for (int i = 0; i < 8; i++) {
        f[i] = __bfloat1622float2(*reinterpret_cast<__nv_bfloat162*>(&w[i]));
        s += f[i].x + f[i].y;
    }
#pragma unroll
    for (int o = 16; o > 0; o >>= 1) s += __shfl_xor_sync(0xffffffffu, s, o);
    float inv = __fdividef(1.0f, s);
#pragma unroll
    for (int i = 0; i < 8; i++) {
        __nv_bfloat162 p = __floats2bfloat162_rn(f[i].x * inv, f[i].y * inv);
        w[i] = *reinterpret_cast<uint32_t*>(&p);
    }
    ((uint4*)row)[lane]      = make_uint4(w[0], w[1], w[2], w[3]);
    ((uint4*)row)[lane + 32] = make_uint4(w[4], w[5], w[6], w[7]);
}

// ---------------- K5: sparse cycle (pure FMA) + fused loss ----------------
__global__ void __launch_bounds__(256) k_cyc() {
    __shared__ float sfx[K_], sfy[K_];
    __shared__ float red[256];
    int nm = blockIdx.x, by = blockIdx.y;
    int n = nm / M_;
    int tid = threadIdx.x, w = tid >> 5, lane = tid & 31;
    for (int i = tid; i < K_; i += 256) {
        sfx[i] = g_fx[n * K_ + i];
        sfy[i] = g_fy[n * K_ + i];
    }
    __syncthreads();

    float part = 0.f;
#pragma unroll 1
    for (int i = 0; i < 4; i++) {
        int k = by * 32 + w * 4 + i;
        float rkk = g_rk[nm * K_ + k];
        float acc[16];
#pragma unroll
        for (int j = 0; j < 16; j++) acc[j] = 0.f;

        for (int ch = 0; ch < NCH; ch++) {
            int base = (nm * NCH + ch) * K_ + k;
            int cnt = g_cnt[base];
            const uint2* cl = g_cand + (size_t)base * CAP;
            if (cnt == 0) continue;
            uint2 ce = cl[0];
            for (int c = 0; c < cnt; c++) {
                uint2 ce_next = (c + 1 < cnt) ? cl[c + 1] : ce;   // prefetch
                float wv = __uint_as_float(ce.y) * rkk;           // A[k,v]
                const uint32_t* row =
                    (const uint32_t*)(g_bt + ((size_t)nm * V_ + ce.x) * K_);
                uint32_t rw[8];
#pragma unroll
                for (int j = 0; j < 8; j++) rw[j] = __ldg(&row[j * 32 + lane]);
#pragma unroll
                for (int j = 0; j < 8; j++) {
                    float2 f = __bfloat1622float2(*reinterpret_cast<__nv_bfloat162*>(&rw[j]));
                    acc[2 * j]     = fmaf(wv, f.x, acc[2 * j]);
                    acc[2 * j + 1] = fmaf(wv, f.y, acc[2 * j + 1]);
                }
                ce = ce_next;
            }
        }

        float xk = sfx[k], yk = sfy[k];
#pragma unroll
        for (int j = 0; j < 8; j++) {
            int q0 = 2 * (j * 32 + lane);
            float dx0 = xk - sfx[q0], dy0 = yk - sfy[q0];
            float dist0 = fmaf(dx0, dx0, dy0 * dy0);
            float wt0 = dist0 * acc[2 * j];
            part = fmaf(wt0, wt0, part);
            float dx1 = xk - sfx[q0 + 1], dy1 = yk - sfy[q0 + 1];
            float dist1 = fmaf(dx1, dx1, dy1 * dy1);
            float wt1 = dist1 * acc[2 * j + 1];
            part = fmaf(wt1, wt1, part);
        }
    }
    red[tid] = part;
    __syncthreads();
    for (int o = 128; o > 0; o >>= 1) {
        if (tid < o) red[tid] += red[tid + o];
        __syncthreads();
    }
    if (tid == 0) g_partial[nm * CYB + by] = red[0];
}

// ---------------- K6: final sqrt + mean ----------------
__global__ void k_final(float* __restrict__ out) {
    int t = threadIdx.x;           // 32 threads, one per nm
    float s = 0.f;
#pragma unroll
    for (int pr = 0; pr < CYB; pr++) s += g_partial[t * CYB + pr];
    float l = sqrtf(s);
#pragma unroll
    for (int o = 16; o > 0; o >>= 1) l += __shfl_xor_sync(0xffffffffu, l, o);
    if (t == 0) out[0] = l / (float)NM_;
}

// ---------------- launch ----------------
extern "C" void kernel_launch(void* const* d_in, const int* in_sizes, int n_in,
                              void* d_out, int out_size) {
    const float* pix  = (const float*)d_in[0];
    const float* mesh = (const float*)d_in[1];
    const void*  idx  = d_in[2];
    float* out = (float*)d_out;
    (void)in_sizes; (void)n_in; (void)out_size;

    k_detect<<<1, 256>>>((const int*)idx);
    k_sample<<<(N_ * K_ + 255) / 256, 256>>>(pix, idx);
    k_prep<<<2, 256>>>();
    k_pass1<<<dim3(NM_, NCH), 512>>>(mesh);    // ncu capture slot
    k_comb<<<(NM_ * K_ + 255) / 256, 256>>>();
    k_norm<<<dim3(NM_, (V_ + 7) / 8), 256>>>();
    k_cyc<<<dim3(NM_, CYB), 256>>>();
    k_final<<<1, 32>>>(out);
}

// round 16
// speedup vs baseline: 2.8367x; 1.2950x over previous
#include <cuda_runtime.h>
#include <cuda_bf16.h>
#include <cstdint>
#include <cstddef>

// ---------------- problem constants ----------------
constexpr int N_  = 16;
constexpr int D_  = 16;
constexpr int S_  = 112;
constexpr int SS_ = S_ * S_;          // 12544
constexpr int M_  = 2;
constexpr int V_  = 7829;
constexpr int K_  = 512;
constexpr int NM_ = N_ * M_;          // 32
constexpr int NCH = 8;                // v-chunks
constexpr int VCH = (V_ + NCH - 1) / NCH;   // 979
constexpr int CAP = 40;               // candidate slots per (k, chunk)
constexpr int VT  = 128;              // smem v-tile
constexpr int CYB = 16;               // k_cyc grid.y
constexpr float ZS     = 28.853900817779268f;  // 20 * log2(e): z = ZS * sim
constexpr float SHZ    = 86.561702453337804f;  // 60 * log2(e): fixed shift (cancels)
constexpr float ZMARG  = 18.755035531556524f;  // 13 * log2(e): keep z > zmax - ZMARG

// ---------------- static device scratch ----------------
__device__ __nv_bfloat16 g_bt[(size_t)NM_ * V_ * K_];   // [nm][v][k] e-tilde (unnormalized)
__device__ float g_rcs[(size_t)NM_ * V_];               // 1 / column sum
__device__ float g_sampled[N_ * K_ * D_];
__device__ float g_fx[N_ * K_], g_fy[N_ * K_];
__device__ float g_rpmax[NM_ * NCH * K_];               // chunk max (z units)
__device__ float g_rpsum[NM_ * NCH * K_];               // chunk sigma (2^(z-zm) sums)
__device__ float g_rk[NM_ * K_];                        // 1/rsum[k]
__device__ int   g_cnt[NM_ * NCH * K_];
__device__ uint2 g_cand[(size_t)NM_ * NCH * K_ * CAP];  // {v, z} then {v, a}
__device__ float g_partial[NM_ * CYB];
__device__ int   g_is64;

static __device__ __forceinline__ float ex2(float x) {
    float r;
    asm("ex2.approx.ftz.f32 %0, %1;" : "=f"(r) : "f"(x));
    return r;
}

// 16-term dot: pre-scaled sampled row (regs) x mesh row (4 float4 from smem)
static __device__ __forceinline__ float dot16s(const float* sk, const float4* mv) {
    float4 m0 = mv[0], m1 = mv[1], m2 = mv[2], m3 = mv[3];
    float s0 =          sk[0]  * m0.x;   s0 = fmaf(sk[1],  m0.y, s0);
    float s1 =          sk[2]  * m0.z;   s1 = fmaf(sk[3],  m0.w, s1);
    float s2 =          sk[4]  * m1.x;   s2 = fmaf(sk[5],  m1.y, s2);
    float s3 =          sk[6]  * m1.z;   s3 = fmaf(sk[7],  m1.w, s3);
    s0 = fmaf(sk[8],  m2.x, s0);  s1 = fmaf(sk[9],  m2.y, s1);
    s2 = fmaf(sk[10], m2.z, s2);  s3 = fmaf(sk[11], m2.w, s3);
    s0 = fmaf(sk[12], m3.x, s0);  s1 = fmaf(sk[13], m3.y, s1);
    s2 = fmaf(sk[14], m3.z, s2);  s3 = fmaf(sk[15], m3.w, s3);
    return (s0 + s1) + (s2 + s3);
}

// ---------------- K0: detect int64 vs int32 indices ----------------
__global__ void k_detect(const int* __restrict__ w) {
    __shared__ int s_allzero;
    if (threadIdx.x == 0) s_allzero = 1;
    __syncthreads();
    int nz = 0;
    for (int i = threadIdx.x * 2 + 1; i < N_ * K_; i += blockDim.x * 2)
        if (w[i] != 0) nz = 1;
    if (nz) atomicAnd(&s_allzero, 0);
    __syncthreads();
    if (threadIdx.x == 0) g_is64 = s_allzero;
}

// ---------------- K1: gather + normalize (pre-scaled by ZS) ----------------
__global__ void k_sample(const float* __restrict__ pix, const void* __restrict__ idxraw) {
    int t = blockIdx.x * blockDim.x + threadIdx.x;
    if (t >= N_ * K_) return;
    long long idx;
    if (g_is64) idx = ((const long long*)idxraw)[t];
    else        idx = (long long)((const int*)idxraw)[t];
    int n = t / K_;
    int p = (int)idx;
    g_fx[t] = (float)(p / S_);
    g_fy[t] = (float)(p % S_);
    const float* base = pix + (size_t)n * D_ * SS_ + p;
    float v[16]; float ss = 0.f;
#pragma unroll
    for (int d = 0; d < 16; d++) { v[d] = base[(size_t)d * SS_]; ss = fmaf(v[d], v[d], ss); }
    float inv = ZS / fmaxf(sqrtf(ss), 1e-6f);      // fold 20*log2(e) into the vector
#pragma unroll
    for (int d = 0; d < 16; d++) g_sampled[t * 16 + d] = v[d] * inv;
}

// ---------------- K1b: filler (keeps k_pass1 in the ncu capture slot) ----------------
__global__ void k_prep() {
    int t = blockIdx.x * blockDim.x + threadIdx.x;
    if (t < NM_ * CYB) g_partial[t] = 0.f;
}

// ---------------- K2: single dense pass (z-domain) ----------------
// Per (k,v): z = dot (pre-scaled), store bf16(2^(z-SHZ)), online row stats +
// candidate list in z units. Pointer-increment addressing, no 64-bit muls.
__global__ void __launch_bounds__(512) k_pass1(const float* __restrict__ mesh) {
    __shared__ float4 smesh[VT * 4];      // 8 KB
    int nm = blockIdx.x, ch = blockIdx.y;
    int k  = threadIdx.x;
    int n = nm / M_, m_ = nm % M_;
    float sk[16];
    const float* sp = &g_sampled[(n * K_ + k) * 16];
#pragma unroll
    for (int d = 0; d < 16; d++) sk[d] = sp[d];
    int v0 = ch * VCH;
    int v1 = min(v0 + VCH, V_);
    const float4* mb = (const float4*)(mesh + (size_t)m_ * V_ * D_);
    __nv_bfloat16* bptr = g_bt + (size_t)nm * V_ * K_ + (size_t)v0 * K_ + k;
    int cbase = (nm * NCH + ch) * K_ + k;
    uint2* cl = g_cand + (size_t)cbase * CAP;

    float zm = -1e30f, sigma = 0.f, thr = -1e30f;
    int cnt = 0;

    for (int tb = v0; tb < v1; tb += VT) {
        int nv = min(VT, v1 - tb);
        for (int i = k; i < nv * 4; i += 512) smesh[i] = mb[(size_t)tb * 4 + i];
        __syncthreads();
#pragma unroll 4
        for (int iv = 0; iv < nv; iv++) {
            float z = dot16s(sk, &smesh[iv * 4]);
            *bptr = __float2bfloat16(ex2(z - SHZ));
            bptr += K_;
            if (z > thr) {
                if (z > zm) { sigma = fmaf(sigma, ex2(zm - z), 1.0f); zm = z; thr = z - ZMARG; }
                else sigma += ex2(z - zm);
                if (cnt >= CAP) {               // rare: compact in place
                    int j = 0;
                    for (int i2 = 0; i2 < cnt; i2++) {
                        uint2 e = cl[i2];
                        if (__uint_as_float(e.y) > thr) cl[j++] = e;
                    }
                    cnt = j;
                }
                if (cnt < CAP) { cl[cnt] = make_uint2((unsigned)(tb + iv), __float_as_uint(z)); cnt++; }
            }
        }
        __syncthreads();
    }
    g_rpmax[cbase] = zm;
    g_rpsum[cbase] = sigma;
    g_cnt[cbase] = cnt;
}

// ---------------- K3: combine chunks -> rk; finalize candidate lists ----------------
__global__ void k_comb() {
    int t = blockIdx.x * blockDim.x + threadIdx.x;
    if (t >= NM_ * K_) return;
    int nm = t / K_, k = t % K_;
    float zstar = -1e30f;
#pragma unroll
    for (int c = 0; c < NCH; c++)
        zstar = fmaxf(zstar, g_rpmax[(nm * NCH + c) * K_ + k]);
    float sig = 0.f;
#pragma unroll
    for (int c = 0; c < NCH; c++) {
        int b = (nm * NCH + c) * K_ + k;
        sig += g_rpsum[b] * ex2(g_rpmax[b] - zstar);
    }
    g_rk[t] = 1.0f / sig;
    float thr = zstar - ZMARG;
#pragma unroll
    for (int c = 0; c < NCH; c++) {
        int b = (nm * NCH + c) * K_ + k;
        int cn = g_cnt[b];
        uint2* cl = g_cand + (size_t)b * CAP;
        int out = 0;
        for (int i = 0; i < cn; i++) {
            uint2 e = cl[i];
            float z = __uint_as_float(e.y);
            if (z > thr)
                cl[out++] = make_uint2(e.x, __float_as_uint(ex2(z - zstar)));
        }
        g_cnt[b] = out;
    }
}

// ---------------- K4: column sums (read-only) -> 1/csum ----------------
__global__ void __launch_bounds__(256) k_csum() {
    int nm = blockIdx.x;
    int v  = blockIdx.y * 8 + (threadIdx.x >> 5);
    int lane = threadIdx.x & 31;
    if (v >= V_) return;
    const uint4* row = (const uint4*)(g_bt + ((size_t)nm * V_ + v) * K_);
    uint4 a = __ldg(&row[lane]);
    uint4 b = __ldg(&row[lane + 32]);
    uint32_t w[8] = {a.x, a.y, a.z, a.w, b.x, b.y, b.z, b.w};
    float s = 0.f;
#pragma unroll
    for (int i = 0; i < 8; i++) {
        float2 f = __bfloat1622float2(*reinterpret_cast<__nv_bfloat162*>(&w[i]));
        s += f.x + f.y;
    }
#pragma unroll
    for (int o = 16; o > 0; o >>= 1) s += __shfl_xor_sync(0xffffffffu, s, o);
    if (lane == 0) g_rcs[(size_t)nm * V_ + v] = __fdividef(1.0f, s);
}

// ---------------- K5: sparse cycle (normalization folded in) ----------------
__global__ void __launch_bounds__(256) k_cyc() {
    __shared__ float sfx[K_], sfy[K_];
    __shared__ float red[256];
    int nm = blockIdx.x, by = blockIdx.y;
    int n = nm / M_;
    int tid = threadIdx.x, w = tid >> 5, lane = tid & 31;
    for (int i = tid; i < K_; i += 256) {
        sfx[i] = g_fx[n * K_ + i];
        sfy[i] = g_fy[n * K_ + i];
    }
    __syncthreads();

    float part = 0.f;
#pragma unroll 1
    for (int i = 0; i < 4; i++) {
        int k = by * 32 + w * 4 + i;
        float rkk = g_rk[nm * K_ + k];
        float acc[16];
#pragma unroll
        for (int j = 0; j < 16; j++) acc[j] = 0.f;

        for (int ch = 0; ch < NCH; ch++) {
            int base = (nm * NCH + ch) * K_ + k;
            int cnt = g_cnt[base];
            const uint2* cl = g_cand + (size_t)base * CAP;
            if (cnt == 0) continue;
            uint2 ce = cl[0];
            for (int c = 0; c < cnt; c++) {
                uint2 ce_next = (c + 1 < cnt) ? cl[c + 1] : ce;   // prefetch
                float rc = __ldg(&g_rcs[(size_t)nm * V_ + ce.x]);
                float wv = __uint_as_float(ce.y) * rkk * rc;      // A[k,v] * 1/csum
                const uint32_t* row =
                    (const uint32_t*)(g_bt + ((size_t)nm * V_ + ce.x) * K_);
                uint32_t rw[8];
#pragma unroll
                for (int j = 0; j < 8; j++) rw[j] = __ldg(&row[j * 32 + lane]);
#pragma unroll
                for (int j = 0; j < 8; j++) {
                    float2 f = __bfloat1622float2(*reinterpret_cast<__nv_bfloat162*>(&rw[j]));
                    acc[2 * j]     = fmaf(wv, f.x, acc[2 * j]);
                    acc[2 * j + 1] = fmaf(wv, f.y, acc[2 * j + 1]);
                }
                ce = ce_next;
            }
        }

        float xk = sfx[k], yk = sfy[k];
#pragma unroll
        for (int j = 0; j < 8; j++) {
            int q0 = 2 * (j * 32 + lane);
            float dx0 = xk - sfx[q0], dy0 = yk - sfy[q0];
            float dist0 = fmaf(dx0, dx0, dy0 * dy0);
            float wt0 = dist0 * acc[2 * j];
            part = fmaf(wt0, wt0, part);
            float dx1 = xk - sfx[q0 + 1], dy1 = yk - sfy[q0 + 1];
            float dist1 = fmaf(dx1, dx1, dy1 * dy1);
            float wt1 = dist1 * acc[2 * j + 1];
            part = fmaf(wt1, wt1, part);
        }
    }
    red[tid] = part;
    __syncthreads();
    for (int o = 128; o > 0; o >>= 1) {
        if (tid < o) red[tid] += red[tid + o];
        __syncthreads();
    }
    if (tid == 0) g_partial[nm * CYB + by] = red[0];
}

// ---------------- K6: final sqrt + mean ----------------
__global__ void k_final(float* __restrict__ out) {
    int t = threadIdx.x;           // 32 threads, one per nm
    float s = 0.f;
#pragma unroll
    for (int pr = 0; pr < CYB; pr++) s += g_partial[t * CYB + pr];
    float l = sqrtf(s);
#pragma unroll
    for (int o = 16; o > 0; o >>= 1) l += __shfl_xor_sync(0xffffffffu, l, o);
    if (t == 0) out[0] = l / (float)NM_;
}

// ---------------- launch ----------------
extern "C" void kernel_launch(void* const* d_in, const int* in_sizes, int n_in,
                              void* d_out, int out_size) {
    const float* pix  = (const float*)d_in[0];
    const float* mesh = (const float*)d_in[1];
    const void*  idx  = d_in[2];
    float* out = (float*)d_out;
    (void)in_sizes; (void)n_in; (void)out_size;

    k_detect<<<1, 256>>>((const int*)idx);
    k_sample<<<(N_ * K_ + 255) / 256, 256>>>(pix, idx);
    k_prep<<<2, 256>>>();
    k_pass1<<<dim3(NM_, NCH), 512>>>(mesh);    // ncu capture slot
    k_comb<<<(NM_ * K_ + 255) / 256, 256>>>();
    k_csum<<<dim3(NM_, (V_ + 7) / 8), 256>>>();
    k_cyc<<<dim3(NM_, CYB), 256>>>();
    k_final<<<1, 32>>>(out);
}